// round 3
// baseline (speedup 1.0000x reference)
#include <cuda_runtime.h>
#include <cstdint>

// NodeDropout: out[e] = values[e] * keep[src[e]] * keep[dst[e]]
// edge_index: int32 [2, E]
// values:     float [E]
// nodes_flag: [N] stored as a 4-byte type (int32 0/1 or float32 0.0/1.0).
//             We read raw 32-bit words and test != 0 — correct for both.
// out:        float [E]

__global__ void node_dropout_kernel(const int* __restrict__ ei,
                                    const float* __restrict__ vals,
                                    const unsigned int* __restrict__ flags,
                                    float* __restrict__ out,
                                    int E)
{
    int i = blockIdx.x * blockDim.x + threadIdx.x;
    int base = i * 4;
    if (base + 3 < E) {
        int4   s = *reinterpret_cast<const int4*>(ei + base);      // src row
        int4   d = *reinterpret_cast<const int4*>(ei + E + base);  // dst row
        float4 v = *reinterpret_cast<const float4*>(vals + base);

        // 8 independent 4B gathers -> MLP hides L2 latency (~240 cyc).
        unsigned int fs0 = flags[s.x];
        unsigned int fs1 = flags[s.y];
        unsigned int fs2 = flags[s.z];
        unsigned int fs3 = flags[s.w];
        unsigned int fd0 = flags[d.x];
        unsigned int fd1 = flags[d.y];
        unsigned int fd2 = flags[d.z];
        unsigned int fd3 = flags[d.w];

        float4 r;
        r.x = (fs0 | fd0) ? 0.0f : v.x;
        r.y = (fs1 | fd1) ? 0.0f : v.y;
        r.z = (fs2 | fd2) ? 0.0f : v.z;
        r.w = (fs3 | fd3) ? 0.0f : v.w;

        *reinterpret_cast<float4*>(out + base) = r;
    } else if (base < E) {
        for (int e = base; e < E; ++e) {
            int s = ei[e];
            int d = ei[E + e];
            out[e] = (flags[s] | flags[d]) ? 0.0f : vals[e];
        }
    }
}

extern "C" void kernel_launch(void* const* d_in, const int* in_sizes, int n_in,
                              void* d_out, int out_size)
{
    const int*          ei    = (const int*)d_in[0];          // [2, E] int32
    const float*        vals  = (const float*)d_in[1];        // [E] float32
    const unsigned int* flags = (const unsigned int*)d_in[2]; // [N] 4-byte 0/nonzero
    float* out = (float*)d_out;

    int E = in_sizes[1]; // element count of values == number of edges

    int threads = 256;
    int elems = (E + 3) / 4;              // 4 edges per thread
    int blocks = (elems + threads - 1) / threads;
    node_dropout_kernel<<<blocks, threads>>>(ei, vals, flags, out, E);
}

// round 6
// speedup vs baseline: 2.3492x; 2.3492x over previous
#include <cuda_runtime.h>
#include <cstdint>

// NodeDropout: out[e] = values[e] unless src or dst node dropped.
// Strategy: pack the 4B-per-node flag table into a 1-bit-per-node bitmask
// (125 KB for 1M nodes), stage it in SHARED memory per CTA, and gather via
// LDS (32 random words/cycle through the smem crossbar) instead of L1tex
// (1 random wavefront/cycle) — which was the R3 bottleneck (L1=90%).

#define MAX_BIT_WORDS 65536  // supports up to 2,097,152 nodes
__device__ unsigned int g_bits[MAX_BIT_WORDS];

// ---- pre-kernel: pack flags (4-byte 0/nonzero) into bitmask via ballot ----
__global__ void pack_flags_kernel(const unsigned int* __restrict__ flags,
                                  int N, int nwords)
{
    int t = blockIdx.x * blockDim.x + threadIdx.x;
    int w = t >> 5;            // one warp per output word
    int lane = t & 31;
    if (w >= nwords) return;
    int idx = w * 32 + lane;
    unsigned int f = (idx < N) ? flags[idx] : 0u;
    unsigned int ballot = __ballot_sync(0xFFFFFFFFu, f != 0u);
    if (lane == 0) g_bits[w] = ballot;
}

// ---- main kernel: one CTA/SM, bitmask in smem, LDS gathers ----
__global__ void __launch_bounds__(1024, 1)
node_dropout_kernel(const int* __restrict__ ei,
                    const float* __restrict__ vals,
                    float* __restrict__ out,
                    int E, int nwords)
{
    extern __shared__ unsigned int bits[];
    // cooperative copy of the bitmask into shared (coalesced, L2-served)
    for (int i = threadIdx.x; i < nwords; i += blockDim.x)
        bits[i] = g_bits[i];
    __syncthreads();

    int nvec = E >> 2;  // groups of 4 edges
    int stride = gridDim.x * blockDim.x;
    for (int g = blockIdx.x * blockDim.x + threadIdx.x; g < nvec; g += stride) {
        int base = g * 4;
        int4   s = *reinterpret_cast<const int4*>(ei + base);      // src row
        int4   d = *reinterpret_cast<const int4*>(ei + E + base);  // dst row
        float4 v = *reinterpret_cast<const float4*>(vals + base);

        unsigned int m0 = (bits[s.x >> 5] >> (s.x & 31)) | (bits[d.x >> 5] >> (d.x & 31));
        unsigned int m1 = (bits[s.y >> 5] >> (s.y & 31)) | (bits[d.y >> 5] >> (d.y & 31));
        unsigned int m2 = (bits[s.z >> 5] >> (s.z & 31)) | (bits[d.z >> 5] >> (d.z & 31));
        unsigned int m3 = (bits[s.w >> 5] >> (s.w & 31)) | (bits[d.w >> 5] >> (d.w & 31));

        float4 r;
        r.x = (m0 & 1u) ? 0.0f : v.x;
        r.y = (m1 & 1u) ? 0.0f : v.y;
        r.z = (m2 & 1u) ? 0.0f : v.z;
        r.w = (m3 & 1u) ? 0.0f : v.w;

        *reinterpret_cast<float4*>(out + base) = r;
    }

    // scalar tail (E % 4 edges), block 0 thread 0
    if (blockIdx.x == 0 && threadIdx.x == 0) {
        for (int e = nvec * 4; e < E; ++e) {
            int s = ei[e];
            int d = ei[E + e];
            unsigned int m = (bits[s >> 5] >> (s & 31)) | (bits[d >> 5] >> (d & 31));
            out[e] = (m & 1u) ? 0.0f : vals[e];
        }
    }
}

extern "C" void kernel_launch(void* const* d_in, const int* in_sizes, int n_in,
                              void* d_out, int out_size)
{
    const int*          ei    = (const int*)d_in[0];          // [2, E] int32
    const float*        vals  = (const float*)d_in[1];        // [E] float32
    const unsigned int* flags = (const unsigned int*)d_in[2]; // [N] 4-byte 0/nonzero
    float* out = (float*)d_out;

    int E = in_sizes[1];
    int N = in_sizes[2];
    int nwords = (N + 31) / 32;

    int num_sms = 0;
    cudaDeviceGetAttribute(&num_sms, cudaDevAttrMultiProcessorCount, 0);
    if (num_sms <= 0) num_sms = 148;

    size_t smem_bytes = (size_t)nwords * sizeof(unsigned int);
    cudaFuncSetAttribute(node_dropout_kernel,
                         cudaFuncAttributeMaxDynamicSharedMemorySize,
                         (int)smem_bytes);

    // 1) pack flags -> bitmask (one warp per 32 nodes)
    {
        int total_threads = nwords * 32;
        int threads = 256;
        int blocks = (total_threads + threads - 1) / threads;
        pack_flags_kernel<<<blocks, threads>>>(flags, N, nwords);
    }

    // 2) masked copy with smem-resident bitmask, one CTA per SM
    node_dropout_kernel<<<num_sms, 1024, smem_bytes>>>(ei, vals, out, E, nwords);
}

// round 8
// speedup vs baseline: 2.3751x; 1.0110x over previous
#include <cuda_runtime.h>
#include <cstdint>

// NodeDropout: out[e] = values[e] unless src or dst node dropped.
// R6 design (smem bitmask + LDS gathers) + 2x unroll for more MLP:
// each iteration issues 6 independent 16B streaming loads before the
// dependent LDS/select/store chain, raising outstanding-load count and
// pushing DRAM utilization toward the ~6.4 TB/s achievable ceiling.

#define MAX_BIT_WORDS 65536  // supports up to 2,097,152 nodes
__device__ unsigned int g_bits[MAX_BIT_WORDS];

// ---- pre-kernel: pack flags (4-byte 0/nonzero) into bitmask via ballot ----
__global__ void pack_flags_kernel(const unsigned int* __restrict__ flags,
                                  int N, int nwords)
{
    int t = blockIdx.x * blockDim.x + threadIdx.x;
    int w = t >> 5;
    int lane = t & 31;
    if (w >= nwords) return;
    int idx = w * 32 + lane;
    unsigned int f = (idx < N) ? flags[idx] : 0u;
    unsigned int ballot = __ballot_sync(0xFFFFFFFFu, f != 0u);
    if (lane == 0) g_bits[w] = ballot;
}

__device__ __forceinline__ unsigned int bit_of(const unsigned int* bits, int i)
{
    return (bits[i >> 5] >> (i & 31)) & 1u;
}

// ---- main kernel: one CTA/SM, bitmask in smem, LDS gathers, 8 edges/iter ----
__global__ void __launch_bounds__(1024, 1)
node_dropout_kernel(const int* __restrict__ ei,
                    const float* __restrict__ vals,
                    float* __restrict__ out,
                    int E, int nwords)
{
    extern __shared__ unsigned int bits[];
    for (int i = threadIdx.x; i < nwords; i += blockDim.x)
        bits[i] = g_bits[i];
    __syncthreads();

    int nvec8 = E >> 3;  // groups of 8 edges
    int stride = gridDim.x * blockDim.x;
    for (int g = blockIdx.x * blockDim.x + threadIdx.x; g < nvec8; g += stride) {
        int base = g * 8;
        // 6 independent streaming loads issued up front (MLP)
        int4   sA = *reinterpret_cast<const int4*>(ei + base);
        int4   sB = *reinterpret_cast<const int4*>(ei + base + 4);
        int4   dA = *reinterpret_cast<const int4*>(ei + E + base);
        int4   dB = *reinterpret_cast<const int4*>(ei + E + base + 4);
        float4 vA = *reinterpret_cast<const float4*>(vals + base);
        float4 vB = *reinterpret_cast<const float4*>(vals + base + 4);

        float4 rA, rB;
        rA.x = (bit_of(bits, sA.x) | bit_of(bits, dA.x)) ? 0.0f : vA.x;
        rA.y = (bit_of(bits, sA.y) | bit_of(bits, dA.y)) ? 0.0f : vA.y;
        rA.z = (bit_of(bits, sA.z) | bit_of(bits, dA.z)) ? 0.0f : vA.z;
        rA.w = (bit_of(bits, sA.w) | bit_of(bits, dA.w)) ? 0.0f : vA.w;
        rB.x = (bit_of(bits, sB.x) | bit_of(bits, dB.x)) ? 0.0f : vB.x;
        rB.y = (bit_of(bits, sB.y) | bit_of(bits, dB.y)) ? 0.0f : vB.y;
        rB.z = (bit_of(bits, sB.z) | bit_of(bits, dB.z)) ? 0.0f : vB.z;
        rB.w = (bit_of(bits, sB.w) | bit_of(bits, dB.w)) ? 0.0f : vB.w;

        *reinterpret_cast<float4*>(out + base)     = rA;
        *reinterpret_cast<float4*>(out + base + 4) = rB;
    }

    // scalar tail (E % 8 edges), block 0 thread 0
    if (blockIdx.x == 0 && threadIdx.x == 0) {
        for (int e = nvec8 * 8; e < E; ++e) {
            int s = ei[e];
            int d = ei[E + e];
            out[e] = (bit_of(bits, s) | bit_of(bits, d)) ? 0.0f : vals[e];
        }
    }
}

extern "C" void kernel_launch(void* const* d_in, const int* in_sizes, int n_in,
                              void* d_out, int out_size)
{
    const int*          ei    = (const int*)d_in[0];          // [2, E] int32
    const float*        vals  = (const float*)d_in[1];        // [E] float32
    const unsigned int* flags = (const unsigned int*)d_in[2]; // [N] 4-byte 0/nonzero
    float* out = (float*)d_out;

    int E = in_sizes[1];
    int N = in_sizes[2];
    int nwords = (N + 31) / 32;

    int num_sms = 0;
    cudaDeviceGetAttribute(&num_sms, cudaDevAttrMultiProcessorCount, 0);
    if (num_sms <= 0) num_sms = 148;

    size_t smem_bytes = (size_t)nwords * sizeof(unsigned int);
    cudaFuncSetAttribute(node_dropout_kernel,
                         cudaFuncAttributeMaxDynamicSharedMemorySize,
                         (int)smem_bytes);

    // 1) pack flags -> bitmask
    {
        int total_threads = nwords * 32;
        int threads = 256;
        int blocks = (total_threads + threads - 1) / threads;
        pack_flags_kernel<<<blocks, threads>>>(flags, N, nwords);
    }

    // 2) masked copy with smem-resident bitmask, one CTA per SM
    node_dropout_kernel<<<num_sms, 1024, smem_bytes>>>(ei, vals, out, E, nwords);
}